// round 1
// baseline (speedup 1.0000x reference)
#include <cuda_runtime.h>
#include <cstdint>

#define DIM 128
#define LEVELS_HALF 8.0f
#define LAPLACE_C 0.456f
#define EPS 1e-8f
#define SQRT_DIM 11.313708498984761f      /* sqrt(128) */
#define INV_SQRT_DIM 0.08838834764831845f /* 1/sqrt(128) */

__global__ __launch_bounds__(256) void turboquant_kernel(
    const float* __restrict__ x,
    const float* __restrict__ signs,
    float* __restrict__ out,
    int nrows)
{
    const int warp = (blockIdx.x * blockDim.x + threadIdx.x) >> 5;
    const int lane = threadIdx.x & 31;
    if (warp >= nrows) return;

    // ---- load signs for this lane's 4 elements (L1-resident, 512B total) ----
    const float4 sv = __ldg(reinterpret_cast<const float4*>(signs) + lane);
    float s[4];
    s[0] = (sv.x >= 0.5f) ? 1.0f : -1.0f;
    s[1] = (sv.y >= 0.5f) ? 1.0f : -1.0f;
    s[2] = (sv.z >= 0.5f) ? 1.0f : -1.0f;
    s[3] = (sv.w >= 0.5f) ? 1.0f : -1.0f;

    // ---- load row (coalesced float4) and apply sign flip ----
    const float4 xv = __ldg(reinterpret_cast<const float4*>(x) + (size_t)warp * 32 + lane);
    float v[4];
    v[0] = xv.x * s[0];
    v[1] = xv.y * s[1];
    v[2] = xv.z * s[2];
    v[3] = xv.w * s[3];

    // ================= forward FWHT (order of stages commutes) =============
    // local stage h=1: pairs (0,1),(2,3)
    {
        float a, b;
        a = v[0]; b = v[1]; v[0] = a + b; v[1] = a - b;
        a = v[2]; b = v[3]; v[2] = a + b; v[3] = a - b;
        // local stage h=2: pairs (0,2),(1,3)
        a = v[0]; b = v[2]; v[0] = a + b; v[2] = a - b;
        a = v[1]; b = v[3]; v[1] = a + b; v[3] = a - b;
    }
    // cross-lane stages: xor masks 1..16 (element stride 4..64)
#pragma unroll
    for (int m = 1; m <= 16; m <<= 1) {
#pragma unroll
        for (int i = 0; i < 4; i++) {
            float p = __shfl_xor_sync(0xffffffffu, v[i], m);
            v[i] = (lane & m) ? (p - v[i]) : (v[i] + p);
        }
    }
#pragma unroll
    for (int i = 0; i < 4; i++) v[i] *= INV_SQRT_DIM;

    // ================= row statistics (two fused warp reductions) ==========
    float ss = v[0] * v[0] + v[1] * v[1] + v[2] * v[2] + v[3] * v[3];
    float sa = fabsf(v[0]) + fabsf(v[1]) + fabsf(v[2]) + fabsf(v[3]);
#pragma unroll
    for (int m = 16; m >= 1; m >>= 1) {
        ss += __shfl_xor_sync(0xffffffffu, ss, m);
        sa += __shfl_xor_sync(0xffffffffu, sa, m);
    }
    const float norm  = sqrtf(ss);
    const float inv_n = SQRT_DIM / (norm + EPS);      // u = r * inv_n
    // scales = C * mean(|u|) = C * (sa * inv_n) / DIM
    const float scale = LAPLACE_C * (sa * inv_n) * (1.0f / (float)DIM);
    const float qs    = 1.0f / (scale + EPS);
    const float deq   = scale * (norm * INV_SQRT_DIM); // r_hat = q * deq

    // ================= quantize + dequantize (pack/unpack is identity) =====
#pragma unroll
    for (int i = 0; i < 4; i++) {
        float u = v[i] * inv_n;
        float q = rintf(u * qs);                       // round half-to-even
        q = fminf(LEVELS_HALF - 1.0f, fmaxf(-LEVELS_HALF, q));
        v[i] = q * deq;
    }

    // ================= inverse FWHT =========================================
    {
        float a, b;
        a = v[0]; b = v[1]; v[0] = a + b; v[1] = a - b;
        a = v[2]; b = v[3]; v[2] = a + b; v[3] = a - b;
        a = v[0]; b = v[2]; v[0] = a + b; v[2] = a - b;
        a = v[1]; b = v[3]; v[1] = a + b; v[3] = a - b;
    }
#pragma unroll
    for (int m = 1; m <= 16; m <<= 1) {
#pragma unroll
        for (int i = 0; i < 4; i++) {
            float p = __shfl_xor_sync(0xffffffffu, v[i], m);
            v[i] = (lane & m) ? (p - v[i]) : (v[i] + p);
        }
    }

    // ---- normalize, re-apply sign, store (coalesced float4) ----
    float4 ov;
    ov.x = v[0] * INV_SQRT_DIM * s[0];
    ov.y = v[1] * INV_SQRT_DIM * s[1];
    ov.z = v[2] * INV_SQRT_DIM * s[2];
    ov.w = v[3] * INV_SQRT_DIM * s[3];
    reinterpret_cast<float4*>(out)[(size_t)warp * 32 + lane] = ov;
}

extern "C" void kernel_launch(void* const* d_in, const int* in_sizes, int n_in,
                              void* d_out, int out_size)
{
    const float* x     = (const float*)d_in[0];
    const float* signs = (const float*)d_in[1];
    float* out         = (float*)d_out;

    const int nrows = in_sizes[0] / DIM;       // 524288
    const int threads = 256;                   // 8 warps = 8 rows / block
    const int blocks  = (nrows + 7) / 8;
    turboquant_kernel<<<blocks, threads>>>(x, signs, out, nrows);
}

// round 4
// speedup vs baseline: 1.5316x; 1.5316x over previous
#include <cuda_runtime.h>
#include <cstdint>

#define DIM 128
#define LAPLACE_C 0.456f
#define EPS 1e-8f
#define SQRT_DIM 11.313708498984761f      /* sqrt(128) */
#define INV_SQRT_DIM 0.08838834764831845f /* 1/sqrt(128) */

__device__ __forceinline__ float sign_xor(float f, uint32_t bit /*0 or 0x80000000*/) {
    return __uint_as_float(__float_as_uint(f) ^ bit);
}

__global__ __launch_bounds__(256) void turboquant_kernel(
    const float* __restrict__ x,
    const float* __restrict__ signs,
    float* __restrict__ out,
    int nrows)
{
    const int lane = threadIdx.x & 31;
    const int t    = lane & 7;                 // thread-in-row (8 threads/row)
    const int warp = (blockIdx.x * blockDim.x + threadIdx.x) >> 5;
    const int row  = warp * 4 + (lane >> 3);   // 4 rows per warp
    if (row >= nrows) return;

    // ---- build packed sign mask: bit (j*4+i) set => flip sign ----
    // element index covered by (j,i): j*32 + t*4 + i
    const float4* s4 = reinterpret_cast<const float4*>(signs);
    uint32_t smask = 0;
#pragma unroll
    for (int j = 0; j < 4; j++) {
        float4 sg = __ldg(s4 + j * 8 + t);
        if (sg.x < 0.5f) smask |= 1u << (j * 4 + 0);
        if (sg.y < 0.5f) smask |= 1u << (j * 4 + 1);
        if (sg.z < 0.5f) smask |= 1u << (j * 4 + 2);
        if (sg.w < 0.5f) smask |= 1u << (j * 4 + 3);
    }

    // ---- load 16 elements (4 fully-coalesced float4 loads), apply signs ----
    const float4* xr = reinterpret_cast<const float4*>(x) + (size_t)row * 32;
    float v[4][4];
#pragma unroll
    for (int j = 0; j < 4; j++) {
        float4 xv = __ldg(xr + j * 8 + t);
        v[j][0] = sign_xor(xv.x, (smask >> (j * 4 + 0)) << 31);
        v[j][1] = sign_xor(xv.y, (smask >> (j * 4 + 1)) << 31);
        v[j][2] = sign_xor(xv.z, (smask >> (j * 4 + 2)) << 31);
        v[j][3] = sign_xor(xv.w, (smask >> (j * 4 + 3)) << 31);
    }

    // ================= forward FWHT (unnormalized; stage order commutes) ====
    // local bits 0,1 (i within float4)
#pragma unroll
    for (int j = 0; j < 4; j++) {
        float b0 = v[j][0] + v[j][1], b1 = v[j][0] - v[j][1];
        float b2 = v[j][2] + v[j][3], b3 = v[j][2] - v[j][3];
        v[j][0] = b0 + b2; v[j][1] = b1 + b3;
        v[j][2] = b0 - b2; v[j][3] = b1 - b3;
    }
    // cross-lane bits 2,3,4 -> lane xor masks 1,2,4 (stay inside 8-lane group)
#pragma unroll
    for (int m = 1; m <= 4; m <<= 1) {
        const float c = (lane & m) ? -1.0f : 1.0f;
#pragma unroll
        for (int j = 0; j < 4; j++)
#pragma unroll
            for (int i = 0; i < 4; i++) {
                float p = __shfl_xor_sync(0xffffffffu, v[j][i], m);
                v[j][i] = fmaf(v[j][i], c, p);
            }
    }
    // local bits 5,6 (j across float4s)
#pragma unroll
    for (int i = 0; i < 4; i++) {
        float b0 = v[0][i] + v[1][i], b1 = v[0][i] - v[1][i];
        float b2 = v[2][i] + v[3][i], b3 = v[2][i] - v[3][i];
        v[0][i] = b0 + b2; v[1][i] = b1 + b3;
        v[2][i] = b0 - b2; v[3][i] = b1 - b3;
    }

    // ================= row stats (reduction over 8-lane group serves 4 rows) =
    float ss = 0.0f, sa = 0.0f;
#pragma unroll
    for (int j = 0; j < 4; j++)
#pragma unroll
        for (int i = 0; i < 4; i++) {
            ss = fmaf(v[j][i], v[j][i], ss);
            sa += fabsf(v[j][i]);
        }
#pragma unroll
    for (int m = 1; m <= 4; m <<= 1) {
        ss += __shfl_xor_sync(0xffffffffu, ss, m);
        sa += __shfl_xor_sync(0xffffffffu, sa, m);
    }

    // raw = unnormalized H·(s·x);  r = raw/sqrt(D);  norm = |raw|/sqrt(D)
    // u_i = raw_i * inv_ne  (the sqrt(D) factors cancel exactly)
    const float norm   = sqrtf(ss) * INV_SQRT_DIM;
    const float inv_ne = 1.0f / (norm + EPS);
    const float scale  = LAPLACE_C * (1.0f / (float)DIM) * sa * inv_ne;  // C·mean|u|
    const float kk     = inv_ne / (scale + EPS);          // q = rint(raw*kk)
    const float fin    = scale * norm * (1.0f / (float)DIM); // deq·(1/D) for unnorm inv FWHT

    // ================= quantize (pack/unpack is identity -> keep q) =========
#pragma unroll
    for (int j = 0; j < 4; j++)
#pragma unroll
        for (int i = 0; i < 4; i++) {
            float q = rintf(v[j][i] * kk);
            v[j][i] = fminf(7.0f, fmaxf(-8.0f, q));
        }

    // ================= inverse FWHT on q (dequant scale commutes) ===========
#pragma unroll
    for (int j = 0; j < 4; j++) {
        float b0 = v[j][0] + v[j][1], b1 = v[j][0] - v[j][1];
        float b2 = v[j][2] + v[j][3], b3 = v[j][2] - v[j][3];
        v[j][0] = b0 + b2; v[j][1] = b1 + b3;
        v[j][2] = b0 - b2; v[j][3] = b1 - b3;
    }
#pragma unroll
    for (int m = 1; m <= 4; m <<= 1) {
        const float c = (lane & m) ? -1.0f : 1.0f;
#pragma unroll
        for (int j = 0; j < 4; j++)
#pragma unroll
            for (int i = 0; i < 4; i++) {
                float p = __shfl_xor_sync(0xffffffffu, v[j][i], m);
                v[j][i] = fmaf(v[j][i], c, p);
            }
    }
#pragma unroll
    for (int i = 0; i < 4; i++) {
        float b0 = v[0][i] + v[1][i], b1 = v[0][i] - v[1][i];
        float b2 = v[2][i] + v[3][i], b3 = v[2][i] - v[3][i];
        v[0][i] = b0 + b2; v[1][i] = b1 + b3;
        v[2][i] = b0 - b2; v[3][i] = b1 - b3;
    }

    // ---- final scale + sign, coalesced float4 store ----
    float4* orow = reinterpret_cast<float4*>(out) + (size_t)row * 32;
#pragma unroll
    for (int j = 0; j < 4; j++) {
        float4 ov;
        ov.x = sign_xor(v[j][0] * fin, (smask >> (j * 4 + 0)) << 31);
        ov.y = sign_xor(v[j][1] * fin, (smask >> (j * 4 + 1)) << 31);
        ov.z = sign_xor(v[j][2] * fin, (smask >> (j * 4 + 2)) << 31);
        ov.w = sign_xor(v[j][3] * fin, (smask >> (j * 4 + 3)) << 31);
        orow[j * 8 + t] = ov;
    }
}

extern "C" void kernel_launch(void* const* d_in, const int* in_sizes, int n_in,
                              void* d_out, int out_size)
{
    const float* x     = (const float*)d_in[0];
    const float* signs = (const float*)d_in[1];
    float* out         = (float*)d_out;

    const int nrows = in_sizes[0] / DIM;           // 524288
    const int rows_per_block = 32;                 // 8 warps * 4 rows
    const int blocks = (nrows + rows_per_block - 1) / rows_per_block;
    turboquant_kernel<<<blocks, 256>>>(x, signs, out, nrows);
}

// round 5
// speedup vs baseline: 1.6106x; 1.0516x over previous
#include <cuda_runtime.h>
#include <cstdint>

#define DIM 128
#define LAPLACE_C 0.456f
#define EPS 1e-8f
#define INV_SQRT_DIM 0.08838834764831845f /* 1/sqrt(128) */

__device__ uint32_t g_smask[4];

__device__ __forceinline__ float sign_xor(float f, uint32_t bit /*0 or 0x80000000*/) {
    return __uint_as_float(__float_as_uint(f) ^ bit);
}

// Pack signs[d] < 0.5 into 4 ballot words (bit d of word d/32).
__global__ void pack_signs_kernel(const float* __restrict__ signs) {
    const int d = threadIdx.x;               // 0..127
    const uint32_t b = __ballot_sync(0xffffffffu, signs[d] < 0.5f);
    if ((d & 31) == 0) g_smask[d >> 5] = b;
}

__global__ __launch_bounds__(256, 5) void turboquant_kernel(
    const float* __restrict__ x,
    float* __restrict__ out,
    int nrows)
{
    const int lane = threadIdx.x & 31;
    const int t    = lane & 7;                 // thread-in-row (8 threads/row)
    const int warp = (blockIdx.x * blockDim.x + threadIdx.x) >> 5;
    const int row  = warp * 4 + (lane >> 3);   // 4 rows per warp
    if (row >= nrows) return;

    // ---- per-thread sign nibbles: element (j,i) -> index j*32 + t*4 + i ----
    const uint4 sm = *reinterpret_cast<const uint4*>(g_smask);
    uint32_t nib[4];
    nib[0] = (sm.x >> (t * 4)) & 0xF;
    nib[1] = (sm.y >> (t * 4)) & 0xF;
    nib[2] = (sm.z >> (t * 4)) & 0xF;
    nib[3] = (sm.w >> (t * 4)) & 0xF;

    // ---- load 16 elements (4 fully-coalesced float4 loads), apply signs ----
    const float4* xr = reinterpret_cast<const float4*>(x) + (size_t)row * 32;
    float v[4][4];
#pragma unroll
    for (int j = 0; j < 4; j++) {
        float4 xv = __ldg(xr + j * 8 + t);
        v[j][0] = sign_xor(xv.x, (nib[j] & 1u) << 31);
        v[j][1] = sign_xor(xv.y, ((nib[j] >> 1) & 1u) << 31);
        v[j][2] = sign_xor(xv.z, ((nib[j] >> 2) & 1u) << 31);
        v[j][3] = sign_xor(xv.w, ((nib[j] >> 3) & 1u) << 31);
    }

    // ================= forward FWHT (unnormalized; stage order commutes) ====
    // local bits 0,1 (i within float4)
#pragma unroll
    for (int j = 0; j < 4; j++) {
        float b0 = v[j][0] + v[j][1], b1 = v[j][0] - v[j][1];
        float b2 = v[j][2] + v[j][3], b3 = v[j][2] - v[j][3];
        v[j][0] = b0 + b2; v[j][1] = b1 + b3;
        v[j][2] = b0 - b2; v[j][3] = b1 - b3;
    }
    // cross-lane bits 2,3,4 -> lane xor masks 1,2,4 (stay inside 8-lane group)
#pragma unroll
    for (int m = 1; m <= 4; m <<= 1) {
        const float c = (lane & m) ? -1.0f : 1.0f;
#pragma unroll
        for (int j = 0; j < 4; j++)
#pragma unroll
            for (int i = 0; i < 4; i++) {
                float p = __shfl_xor_sync(0xffffffffu, v[j][i], m);
                v[j][i] = fmaf(v[j][i], c, p);
            }
    }
    // local bits 5,6 (j across float4s)
#pragma unroll
    for (int i = 0; i < 4; i++) {
        float b0 = v[0][i] + v[1][i], b1 = v[0][i] - v[1][i];
        float b2 = v[2][i] + v[3][i], b3 = v[2][i] - v[3][i];
        v[0][i] = b0 + b2; v[1][i] = b1 + b3;
        v[2][i] = b0 - b2; v[3][i] = b1 - b3;
    }

    // ================= row stats (reduction over 8-lane group serves 4 rows) =
    float ss = 0.0f, sa = 0.0f;
#pragma unroll
    for (int j = 0; j < 4; j++)
#pragma unroll
        for (int i = 0; i < 4; i++) {
            ss = fmaf(v[j][i], v[j][i], ss);
            sa += fabsf(v[j][i]);
        }
#pragma unroll
    for (int m = 1; m <= 4; m <<= 1) {
        ss += __shfl_xor_sync(0xffffffffu, ss, m);
        sa += __shfl_xor_sync(0xffffffffu, sa, m);
    }

    // raw = unnormalized H·(s·x);  norm = |raw|/sqrt(D);  u_i = raw_i*inv_ne
    const float norm   = sqrtf(ss) * INV_SQRT_DIM;
    const float inv_ne = 1.0f / (norm + EPS);
    const float scale  = LAPLACE_C * (1.0f / (float)DIM) * sa * inv_ne;  // C·mean|u|
    const float kk     = inv_ne / (scale + EPS);             // q = rint(raw*kk)
    const float fin    = scale * norm * (1.0f / (float)DIM); // deq·(1/D)

    // ================= quantize (pack/unpack is identity -> keep q) =========
#pragma unroll
    for (int j = 0; j < 4; j++)
#pragma unroll
        for (int i = 0; i < 4; i++) {
            float q = rintf(v[j][i] * kk);
            v[j][i] = fminf(7.0f, fmaxf(-8.0f, q));
        }

    // ================= inverse FWHT on q (dequant scale commutes) ===========
#pragma unroll
    for (int j = 0; j < 4; j++) {
        float b0 = v[j][0] + v[j][1], b1 = v[j][0] - v[j][1];
        float b2 = v[j][2] + v[j][3], b3 = v[j][2] - v[j][3];
        v[j][0] = b0 + b2; v[j][1] = b1 + b3;
        v[j][2] = b0 - b2; v[j][3] = b1 - b3;
    }
#pragma unroll
    for (int m = 1; m <= 4; m <<= 1) {
        const float c = (lane & m) ? -1.0f : 1.0f;
#pragma unroll
        for (int j = 0; j < 4; j++)
#pragma unroll
            for (int i = 0; i < 4; i++) {
                float p = __shfl_xor_sync(0xffffffffu, v[j][i], m);
                v[j][i] = fmaf(v[j][i], c, p);
            }
    }
#pragma unroll
    for (int i = 0; i < 4; i++) {
        float b0 = v[0][i] + v[1][i], b1 = v[0][i] - v[1][i];
        float b2 = v[2][i] + v[3][i], b3 = v[2][i] - v[3][i];
        v[0][i] = b0 + b2; v[1][i] = b1 + b3;
        v[2][i] = b0 - b2; v[3][i] = b1 - b3;
    }

    // ---- final scale + sign, coalesced float4 store ----
    float4* orow = reinterpret_cast<float4*>(out) + (size_t)row * 32;
#pragma unroll
    for (int j = 0; j < 4; j++) {
        float4 ov;
        ov.x = sign_xor(v[j][0] * fin, (nib[j] & 1u) << 31);
        ov.y = sign_xor(v[j][1] * fin, ((nib[j] >> 1) & 1u) << 31);
        ov.z = sign_xor(v[j][2] * fin, ((nib[j] >> 2) & 1u) << 31);
        ov.w = sign_xor(v[j][3] * fin, ((nib[j] >> 3) & 1u) << 31);
        orow[j * 8 + t] = ov;
    }
}

extern "C" void kernel_launch(void* const* d_in, const int* in_sizes, int n_in,
                              void* d_out, int out_size)
{
    const float* x     = (const float*)d_in[0];
    const float* signs = (const float*)d_in[1];
    float* out         = (float*)d_out;

    const int nrows = in_sizes[0] / DIM;           // 524288
    pack_signs_kernel<<<1, DIM>>>(signs);
    const int rows_per_block = 32;                 // 8 warps * 4 rows
    const int blocks = (nrows + rows_per_block - 1) / rows_per_block;
    turboquant_kernel<<<blocks, 256>>>(x, out, nrows);
}